// round 14
// baseline (speedup 1.0000x reference)
#include <cuda_runtime.h>
#include <math.h>

#define BATCH   64
#define T_LEN   262144
#define STEP    171
#define NSEG    1531
#define NPAIR   766
#define NPAD    768           // padded partials per batch (float4-friendly)

// ---------------- Compile-time tables (no init kernel) ----------------
struct Tables {
    float2 tw[512];   // W512^i = exp(-2*pi*i*I/512)
    float  wp[512];   // folded one-sided A-weight per full-spectrum bin
};

constexpr double PI_D = 3.141592653589793238462643383279502884;

constexpr double tsin_q(double x) {
    double x2 = x * x, term = x, s = x;
    for (int n = 1; n <= 12; ++n) { term *= -x2 / (double)((2*n) * (2*n+1)); s += term; }
    return s;
}
constexpr double tcos_q(double x) {
    double x2 = x * x, term = 1.0, s = 1.0;
    for (int n = 1; n <= 12; ++n) { term *= -x2 / (double)((2*n-1) * (2*n)); s += term; }
    return s;
}
constexpr double tsqrt(double x) {
    double g = (x > 1.0) ? x : 1.0;
    for (int i = 0; i < 64; ++i) g = 0.5 * (g + x / g);
    return g;
}

constexpr Tables make_tables() {
    Tables tb{};
    for (int i = 0; i < 512; ++i) {
        int k = i & 127, q = (i >> 7) & 3;
        double th = PI_D * (double)k / 256.0;
        double c0 = tcos_q(th), s0 = tsin_q(th);
        double c = 0.0, s = 0.0;
        if      (q == 0) { c =  c0; s =  s0; }
        else if (q == 1) { c = -s0; s =  c0; }
        else if (q == 2) { c = -c0; s = -s0; }
        else             { c =  s0; s = -c0; }
        tb.tw[i].x = (float)c;
        tb.tw[i].y = (float)(-s);
        int kp = (i < 256) ? i : (512 - i);
        double w = 0.0;
        if (kp >= 1 && kp <= 243) {
            double f   = (double)kp * (3152.0 / 512.0);
            double fsq = f * f;
            double num = 12194.0 * 12194.0 * fsq * fsq;
            double den = (fsq + 20.6 * 20.6)
                       * tsqrt((fsq + 107.7 * 107.7) * (fsq + 737.9 * 737.9))
                       * (fsq + 12194.0 * 12194.0);
            double r = num / den;
            w = r * r * 1.5848931924611134852;
        }
        tb.wp[i] = (float)w;
    }
    return tb;
}

__device__ const Tables g_tab = make_tables();

// Scratch
__device__ __align__(16) float g_partial[BATCH * NPAD];

// ---------------- Packed f32x2 primitives (Blackwell FFMA2 path) ----------------
typedef unsigned long long p2;

__device__ __forceinline__ p2 pk(float a, float b) {
    p2 r; asm("mov.b64 %0, {%1, %2};" : "=l"(r) : "f"(a), "f"(b)); return r;
}
__device__ __forceinline__ void upk(float& a, float& b, p2 v) {
    asm("mov.b64 {%0, %1}, %2;" : "=f"(a), "=f"(b) : "l"(v));
}
__device__ __forceinline__ p2 f2add(p2 a, p2 b) {
    p2 r; asm("add.rn.f32x2 %0, %1, %2;" : "=l"(r) : "l"(a), "l"(b)); return r;
}
__device__ __forceinline__ p2 f2mul(p2 a, p2 b) {
    p2 r; asm("mul.rn.f32x2 %0, %1, %2;" : "=l"(r) : "l"(a), "l"(b)); return r;
}
__device__ __forceinline__ p2 f2fma(p2 a, p2 b, p2 c) {  // a*b + c
    p2 r; asm("fma.rn.f32x2 %0, %1, %2, %3;" : "=l"(r) : "l"(a), "l"(b), "l"(c)); return r;
}

#define NEG1C 0xBF800000BF800000ULL   // (-1.0f, -1.0f)
__device__ __forceinline__ p2 f2sub(p2 a, p2 b) {   // a - b, single rounding
    return f2fma(b, (p2)NEG1C, a);
}

// Packed DFT-8 over two independent FFT lanes; structure mirrors scalar dft8.
__device__ __forceinline__ void dft8p(p2* xr, p2* xi, p2 Cp, p2 NCp)
{
    p2 e0r=f2add(xr[0],xr[4]), e0i=f2add(xi[0],xi[4]);
    p2 o0r=f2sub(xr[0],xr[4]), o0i=f2sub(xi[0],xi[4]);
    p2 e1r=f2add(xr[1],xr[5]), e1i=f2add(xi[1],xi[5]);
    p2 o1r=f2sub(xr[1],xr[5]), o1i=f2sub(xi[1],xi[5]);
    p2 e2r=f2add(xr[2],xr[6]), e2i=f2add(xi[2],xi[6]);
    p2 o2r=f2sub(xr[2],xr[6]), o2i=f2sub(xi[2],xi[6]);
    p2 e3r=f2add(xr[3],xr[7]), e3i=f2add(xi[3],xi[7]);
    p2 o3r=f2sub(xr[3],xr[7]), o3i=f2sub(xi[3],xi[7]);
    p2 t1r=f2mul(f2add(o1r,o1i),Cp), t1i=f2mul(f2sub(o1i,o1r),Cp);
    p2 t3r=f2mul(f2sub(o3i,o3r),Cp), t3i=f2mul(f2add(o3r,o3i),NCp);
    p2 a0r=f2add(e0r,e2r), a0i=f2add(e0i,e2i);
    p2 a1r=f2sub(e0r,e2r), a1i=f2sub(e0i,e2i);
    p2 a2r=f2add(e1r,e3r), a2i=f2add(e1i,e3i);
    p2 a3r=f2sub(e1r,e3r), a3i=f2sub(e1i,e3i);
    xr[0]=f2add(a0r,a2r); xi[0]=f2add(a0i,a2i);
    xr[4]=f2sub(a0r,a2r); xi[4]=f2sub(a0i,a2i);
    xr[2]=f2add(a1r,a3i); xi[2]=f2sub(a1i,a3r);
    xr[6]=f2sub(a1r,a3i); xi[6]=f2add(a1i,a3r);
    // t2 = (o2i, -o2r) folded into b0/b1
    p2 b0r=f2add(o0r,o2i), b0i=f2sub(o0i,o2r);
    p2 b1r=f2sub(o0r,o2i), b1i=f2add(o0i,o2r);
    p2 b2r=f2add(t1r,t3r), b2i=f2add(t1i,t3i);
    p2 b3r=f2sub(t1r,t3r), b3i=f2sub(t1i,t3i);
    xr[1]=f2add(b0r,b2r); xi[1]=f2add(b0i,b2i);
    xr[5]=f2sub(b0r,b2r); xi[5]=f2sub(b0i,b2i);
    xr[3]=f2add(b1r,b3i); xi[3]=f2sub(b1i,b3r);
    xr[7]=f2sub(b1r,b3i); xi[7]=f2add(b1i,b3r);
}

// Twiddle chain: apply W^{q*n} for q=1..7 from packed base (cw,sw).
__device__ __forceinline__ void chainp(p2* xr, p2* xi, p2 c1, p2 s1)
{
    p2 cw = c1, sw = s1;
    #pragma unroll
    for (int q = 1; q < 8; ++q) {
        // x' = x * (cw + i sw):  re' = re*cw - im*sw ; im' = re*sw + im*cw
        p2 rr = xr[q], ii = xi[q];
        xr[q] = f2sub(f2mul(rr, cw), f2mul(ii, sw));
        xi[q] = f2fma(rr, sw, f2mul(ii, cw));
        p2 nc = f2sub(f2mul(cw, c1), f2mul(sw, s1));
        sw    = f2fma(cw, s1, f2mul(sw, c1));
        cw    = nc;
    }
}

// One 128-thread block = 2 groups x 2 packed pair-FFTs = 4 pair-FFTs (8 segments).
__global__ __launch_bounds__(128) void fft_pair_kernel(const float* __restrict__ x)
{
    // Shared exchange buffers (injective maps, reused with WAR barrier):
    //   Exchange 1: addr = 72*q  + t
    //   Exchange 2: addr = 65*q2 + t
    __shared__ p2 exr[2][576], exi[2][576];
    __shared__ p2 redp[2][2];

    const int g = threadIdx.x >> 6;        // group 0..1
    const int t = threadIdx.x & 63;        // 0..63 within group
    const int jA = blockIdx.x * 4 + 2 * g; // pair A (lane 0)
    const int jB = jA + 1;                 // pair B (lane 1)
    const int b = blockIdx.y;

    const bool actA = jA < NPAIR, actB = jB < NPAIR;
    const bool hbA = (2 * jA + 1) < NSEG, hbB = (2 * jB + 1) < NSEG;
    const float* xA = x + (size_t)b * T_LEN + (size_t)(actA ? jA : 0) * (2 * STEP);
    const float* xB = x + (size_t)b * T_LEN + (size_t)(actB ? jB : 0) * (2 * STEP);

    const float2 w1s = g_tab.tw[t];        // W512^t, coalesced

    p2 re[8], im[8];

    // Load + window (scalar w, identical formula to R13), pack lanes A/B.
    {
        const float ct = w1s.x, st = -w1s.y;
        const float R2 = 0.70710678118654752f;
        const float WC[8] = {1.0f,  R2, 0.0f, -R2, -1.0f, -R2,  0.0f,  R2};
        const float WS[8] = {0.0f,  R2, 1.0f,  R2,  0.0f, -R2, -1.0f, -R2};
        #pragma unroll
        for (int p = 0; p < 8; ++p) {
            int i = t + (p << 6);
            float w = 0.54f - 0.46f * (ct * WC[p] - st * WS[p]);
            float a0 = actA ? xA[i] : 0.0f;
            float b0 = actB ? xB[i] : 0.0f;
            float a1 = (actA && hbA) ? xA[i + STEP] : 0.0f;
            float b1 = (actB && hbB) ? xB[i + STEP] : 0.0f;
            p2 wpk = pk(w, w);
            re[p] = f2mul(pk(a0, b0), wpk);
            im[p] = f2mul(pk(a1, b1), wpk);
        }
    }

    const p2 Cp  = pk( 0.70710678118654752f,  0.70710678118654752f);
    const p2 NCp = pk(-0.70710678118654752f, -0.70710678118654752f);

    // Pass 1: DFT-8 + twiddle W512^{t*q}
    dft8p(re, im, Cp, NCp);
    chainp(re, im, pk(w1s.x, w1s.x), pk(w1s.y, w1s.y));

    // Exchange 1: store 72q+t; load 72qp + m + 8s.
    #pragma unroll
    for (int q = 0; q < 8; ++q) { exr[g][72*q + t] = re[q]; exi[g][72*q + t] = im[q]; }
    __syncthreads();
    const int qp = t >> 3, m = t & 7;
    #pragma unroll
    for (int s = 0; s < 8; ++s) {
        int a = 72 * qp + m + (s << 3);
        re[s] = exr[g][a]; im[s] = exi[g][a];
    }
    __syncthreads();   // WAR guard (buffer reuse)

    // Pass 2: DFT-8 + twiddle W64^{m*q2} (base W512^{8m})
    dft8p(re, im, Cp, NCp);
    {
        const float2 w2s = g_tab.tw[m << 3];
        chainp(re, im, pk(w2s.x, w2s.x), pk(w2s.y, w2s.y));
    }

    // Exchange 2: store 65*q2 + t; load 8qp + r2 + 65m.
    #pragma unroll
    for (int q2 = 0; q2 < 8; ++q2) { exr[g][65*q2 + t] = re[q2]; exi[g][65*q2 + t] = im[q2]; }
    __syncthreads();
    #pragma unroll
    for (int r2 = 0; r2 < 8; ++r2) {
        int a = (qp << 3) + r2 + 65 * m;
        re[r2] = exr[g][a]; im[r2] = exi[g][a];
    }

    // Pass 3: DFT-8. Thread owns bins k = 64*r2 + 8*m + qp (both lanes).
    dft8p(re, im, Cp, NCp);

    const int basek = (m << 3) + qp;
    p2 acc = pk(0.0f, 0.0f);
    #pragma unroll
    for (int r2 = 0; r2 < 8; ++r2) {
        int k = (r2 << 6) + basek;
        float wv = g_tab.wp[k];
        p2 pwr = f2fma(im[r2], im[r2], f2mul(re[r2], re[r2]));
        acc = f2fma(pwr, pk(wv, wv), acc);
    }

    // Reduce 64 threads (packed lanes stay independent; same tree as R13)
    #pragma unroll
    for (int o = 16; o > 0; o >>= 1)
        acc = f2add(acc, __shfl_down_sync(0xffffffffu, acc, o));
    if ((t & 31) == 0) redp[g][t >> 5] = acc;
    __syncthreads();
    if (t == 0) {
        p2 s = f2add(redp[g][0], redp[g][1]);
        float sA, sB; upk(sA, sB, s);
        g_partial[b * NPAD + jA] = sA;     // jA <= 766 < NPAD
        g_partial[b * NPAD + jB] = sB;     // jB <= 767 < NPAD (pad gets 0)
    }
}

// Single block: 16 threads per batch -> band sum -> 10*log10 -> mean over 64.
__global__ __launch_bounds__(1024) void reduce_all_kernel(float cnorm, float* __restrict__ out)
{
    __shared__ float lv[64];
    __shared__ float red[2];
    const int tid = threadIdx.x;
    const int b = tid >> 4;
    const int l = tid & 15;

    const float4* p4 = reinterpret_cast<const float4*>(g_partial + b * NPAD);
    float s = 0.0f;
    #pragma unroll
    for (int i = 0; i < 12; ++i) {
        float4 v = p4[l + (i << 4)];
        s += (v.x + v.y) + (v.z + v.w);
    }
    #pragma unroll
    for (int o = 8; o > 0; o >>= 1) s += __shfl_down_sync(0xffffffffu, s, o, 16);
    if (l == 0) lv[b] = 10.0f * log10f(s * cnorm);
    __syncthreads();

    if (tid < 64) {
        float v = lv[tid];
        #pragma unroll
        for (int o = 16; o > 0; o >>= 1) v += __shfl_down_sync(0xffffffffu, v, o);
        if ((tid & 31) == 0) red[tid >> 5] = v;
    }
    __syncthreads();
    if (tid == 0) out[0] = (red[0] + red[1]) * (1.0f / (float)BATCH);
}

extern "C" void kernel_launch(void* const* d_in, const int* in_sizes, int n_in,
                              void* d_out, int out_size)
{
    const float* x = (const float*)d_in[0];
    float* out = (float*)d_out;

    double wp = 0.0;
    for (int i = 0; i < 512; ++i) {
        double w = 0.54 - 0.46 * cos(2.0 * M_PI * (double)i / 512.0);
        float wf = (float)w;
        wp += (double)wf * (double)wf;
    }
    float cnorm = (float)(1.0 / (wp * 3152.0 * (double)NSEG));

    dim3 grid(192, BATCH);   // 192*4 = 768 pair slots >= 766
    fft_pair_kernel<<<grid, 128>>>(x);
    reduce_all_kernel<<<1, 1024>>>(cnorm, out);
}